// round 10
// baseline (speedup 1.0000x reference)
#include <cuda_runtime.h>
#include <cuda_bf16.h>
#include <cstdint>
#include <cmath>

#define T_LEN 1024
#define NH    512
#define NI    128
#define BSZ   64
#define DT_C  0.1f

// Hoisted input projection scratch: tanh(x @ x2h), [B, T, H] fp32 (134 MB).
__device__ float g_tanhI[(size_t)BSZ * T_LEN * NH];

typedef unsigned long long ull;

// ---------------------------------------------------------------------------
// helpers
// ---------------------------------------------------------------------------
__device__ __forceinline__ uint32_t smem_u32(const void* p) {
    uint32_t a;
    asm("{ .reg .u64 t; cvta.to.shared.u64 t, %1; cvt.u32.u64 %0, t; }" : "=r"(a) : "l"(p));
    return a;
}
__device__ __forceinline__ uint32_t mapa_sc(uint32_t addr, uint32_t rank) {
    uint32_t r;
    asm("mapa.shared::cluster.u32 %0, %1, %2;" : "=r"(r) : "r"(addr), "r"(rank));
    return r;
}
__device__ __forceinline__ void st_dsm_v2(uint32_t addr, ull a, ull b) {
    asm volatile("st.shared::cluster.v2.b64 [%0], {%1, %2};"
                 :: "r"(addr), "l"(a), "l"(b) : "memory");
}
__device__ __forceinline__ void cluster_sync_() {
    asm volatile("barrier.cluster.arrive.aligned;" ::: "memory");
    asm volatile("barrier.cluster.wait.aligned;" ::: "memory");
}
__device__ __forceinline__ void bar_named(int id) {
    asm volatile("bar.sync %0, 256;" :: "r"(id) : "memory");
}
__device__ __forceinline__ ull pack2(float w) {
    ull r;
    asm("mov.b64 %0, {%1, %1};" : "=l"(r) : "f"(w));
    return r;
}
__device__ __forceinline__ void unpack2(float& lo, float& hi, ull v) {
    asm("mov.b64 {%0, %1}, %2;" : "=f"(lo), "=f"(hi) : "l"(v));
}
__device__ __forceinline__ void ffma2(ull& d, ull a, ull b) {
    asm("fma.rn.f32x2 %0, %1, %2, %0;" : "+l"(d) : "l"(a), "l"(b));
}
__device__ __forceinline__ ull addf2(ull a, ull b) {
    ull d;
    asm("add.rn.f32x2 %0, %1, %2;" : "=l"(d) : "l"(a), "l"(b));
    return d;
}
__device__ __forceinline__ void mbar_init(uint32_t addr, uint32_t count) {
    asm volatile("mbarrier.init.shared.b64 [%0], %1;" :: "r"(addr), "r"(count) : "memory");
}
__device__ __forceinline__ void mbar_arrive_remote(uint32_t addr) {
    asm volatile("mbarrier.arrive.release.cluster.shared::cluster.b64 _, [%0];"
                 :: "r"(addr) : "memory");
}
__device__ __forceinline__ void mbar_wait(uint32_t mbar, uint32_t parity) {
    uint32_t done;
    asm volatile(
        "{\n\t.reg .pred p;\n\t"
        "mbarrier.try_wait.parity.acquire.cluster.shared::cta.b64 p, [%1], %2;\n\t"
        "selp.b32 %0, 1, 0, p;\n\t}"
        : "=r"(done) : "r"(mbar), "r"(parity) : "memory");
    if (!done) {
        asm volatile(
            "{\n\t.reg .pred P1;\n\t"
            "W_%=:\n\t"
            "mbarrier.try_wait.parity.acquire.cluster.shared::cta.b64 P1, [%0], %1, 0x989680;\n\t"
            "@P1 bra.uni D_%=;\n\t"
            "bra.uni W_%=;\n\t"
            "D_%=:\n\t}"
            :: "r"(mbar), "r"(parity) : "memory");
    }
}

// ---------------------------------------------------------------------------
// Phase 1: g_tanhI[bt, h] = tanh( x[bt, :] @ x2h[:, h] )
// ---------------------------------------------------------------------------
__global__ void __launch_bounds__(256) phase1_kernel(const float* __restrict__ x,
                                                     const float* __restrict__ x2h) {
    __shared__ float  x_s[16 * 132];
    __shared__ float4 w4_s[128 * 16];
    const int tid = threadIdx.x;
    const int bt0 = blockIdx.x * 16;

    for (int i = tid; i < 512; i += 256) {
        int r = i >> 5, c = i & 31;
        float4 v = *reinterpret_cast<const float4*>(x + (size_t)(bt0 + r) * NI + c * 4);
        *reinterpret_cast<float4*>(x_s + r * 132 + c * 4) = v;
    }

    const int tt = tid & 15;
    const int jc = tid >> 4;
    for (int chunk = 0; chunk < 8; ++chunk) {
        __syncthreads();
        const int jbase = chunk * 64;
        for (int i = tid; i < 2048; i += 256) {
            int k = i >> 4, jq = i & 15;
            w4_s[k * 16 + jq] =
                *reinterpret_cast<const float4*>(x2h + (size_t)k * NH + jbase + jq * 4);
        }
        __syncthreads();
        float a0 = 0.f, a1 = 0.f, a2 = 0.f, a3 = 0.f;
        #pragma unroll 8
        for (int k = 0; k < 128; ++k) {
            float  xv = x_s[tt * 132 + k];
            float4 w  = w4_s[k * 16 + jc];
            a0 = fmaf(xv, w.x, a0); a1 = fmaf(xv, w.y, a1);
            a2 = fmaf(xv, w.z, a2); a3 = fmaf(xv, w.w, a3);
        }
        float4 o = make_float4(tanhf(a0), tanhf(a1), tanhf(a2), tanhf(a3));
        *reinterpret_cast<float4*>(g_tanhI + (size_t)(bt0 + tt) * NH + jbase + jc * 4) = o;
    }
}

// ---------------------------------------------------------------------------
// Phase 2: recurrence. 16 clusters x 8 CTAs x 512 threads = TWO independent
// 256-thread pipelines per CTA (group g handles batch rows {2g, 2g+1}).
// Groups sync only via their own named barrier + per-group mbarriers, so
// one group's exchange latency hides under the other group's compute.
//
// SMEM float layout:
//   [0)      w      64*514 = 32896   (w[j][k], stride 514 for LDS.64 k-pairs)
//   [32896)  hyT    2 g * 2 m * 516  = 2064
//   [34960)  pd     2 g * 256        = 512   (pre dup [j][m]{p,p})
//   [35472)  stg    2 g * 1024       = 2048  ([ks][j] -> {accm0, accm1})
//   [37520)  red    2 g * 1024       = 2048  ([src][klp][m]{k0,k1})
//   [39568)  hyst   2 g * 144        = 288   ([m][kl], stride 72)
//   [39856)  bias   64
//   [39920)  mbars  redM[2] + hyM[2] (8B each) = 8 floats
//   total 39928 floats = 159712 B
// ---------------------------------------------------------------------------
#define WS        514
#define W_OFF     0
#define HYT_OFF   32896
#define PD_OFF    34960
#define STG_OFF   35472
#define RED_OFF   37520
#define HYST_OFF  39568
#define BIAS_OFF  39856
#define MBAR_OFF  39920
#define SMEM_FLOATS 39928
#define SMEM_BYTES  (SMEM_FLOATS * 4)

__global__ void __launch_bounds__(512)
rnn_kernel(const float* __restrict__ h2h, const float* __restrict__ bias,
           const float* __restrict__ gamma_v, const float* __restrict__ eps_v,
           float* __restrict__ out_states, float* __restrict__ out_hy) {
    extern __shared__ float sm[];
    float* bias_s = sm + BIAS_OFF;

    const int tid = threadIdx.x;
    uint32_t rank;
    asm("mov.u32 %0, %%cluster_ctarank;" : "=r"(rank));
    const int m_base = (blockIdx.x >> 3) * 4;
    const int J0 = (int)rank * 64;
    const uint32_t smb = smem_u32(sm);

    // group decomposition
    const int g    = tid >> 8;        // 0 or 1
    const int gtid = tid & 255;
    const int barid = 1 + g;
    const int HYT_G  = HYT_OFF  + g * 1032;
    const int PD_G   = PD_OFF   + g * 256;
    const int STG_G  = STG_OFF  + g * 1024;
    const int RED_G  = RED_OFF  + g * 1024;
    const int HYST_G = HYST_OFF + g * 144;
    const uint32_t redM = smb + MBAR_OFF * 4 + g * 8;
    const uint32_t hyM  = smb + MBAR_OFF * 4 + 16 + g * 8;

    // --- init: weights, bias, zero hyT, mbars ---
    for (int idx = tid; idx < 64 * 512; idx += 512) {
        int k = idx >> 6, jl = idx & 63;
        sm[W_OFF + jl * WS + k] = h2h[(size_t)k * NH + J0 + jl];
    }
    if (tid < 64) bias_s[tid] = bias[J0 + tid];
    for (int i = tid; i < 2064; i += 512) sm[HYT_OFF + i] = 0.f;
    if (tid == 0) {
        mbar_init(smb + MBAR_OFF * 4,      8);   // redM g0
        mbar_init(smb + MBAR_OFF * 4 + 8,  8);   // redM g1
        mbar_init(smb + MBAR_OFF * 4 + 16, 8);   // hyM  g0
        mbar_init(smb + MBAR_OFF * 4 + 24, 8);   // hyM  g1
    }

    // --- per-group thread mappings ---
    const int ks = gtid >> 6;           // GEMM1 k-chunk 0..3 (128 k each)
    const int jg = gtid & 63;           // GEMM1 local j
    const int kp = gtid;                // GEMM2 k-pair 0..255 (k = 2kp, 2kp+1)
    const int kl_u = gtid >> 1;         // update (gtid<128)
    const int m_u  = gtid & 1;
    const int k_own = J0 + kl_u;
    const int bc_r = gtid >> 5, bc_l = gtid & 31;
    const int bc_m = bc_l >> 4, bc_q = bc_l & 15;
    const bool lane0 = (tid & 31) == 0;

    // hoisted DSMEM addresses
    const uint32_t red_tgt = (uint32_t)(kp >> 5);
    const uint32_t red_dst = mapa_sc(smb + RED_G * 4, red_tgt) +
                             (uint32_t)((rank * 128 + (kp & 31) * 4) * 4);
    const uint32_t red_arr = mapa_sc(redM, red_tgt);
    const uint32_t hy_dst  = mapa_sc(smb + HYT_G * 4, (uint32_t)bc_r) +
                             (uint32_t)((bc_m * 516 + J0 + bc_q * 4) * 4);
    const uint32_t hy_arr  = mapa_sc(hyM, (uint32_t)bc_r);

    float hy_r = 0.f, hz_r = 0.f, g_r = 0.f, e_r = 0.f, tI = 0.f;
    size_t row_base = 0;
    if (gtid < 128) {
        g_r = gamma_v[k_own];
        e_r = eps_v[k_own];
        row_base = (size_t)(m_base + 2 * g + m_u) * T_LEN * NH + k_own;
        tI = g_tanhI[row_base];
    }

    __syncthreads();
    cluster_sync_();   // weights, zeroed hyT, mbars visible cluster-wide

    const float* wp1 = sm + W_OFF + jg * WS + ks * 128;
    const float* h0p = sm + HYT_G + 0 * 516 + ks * 128;
    const float* h1p = sm + HYT_G + 1 * 516 + ks * 128;

    for (int t = 0; t < T_LEN; ++t) {
        // ---- wait my group's hy broadcast, then GEMM1 ----
        if (t) mbar_wait(hyM, (uint32_t)((t + 1) & 1));
        {
            ull a0 = 0, a1 = 0;    // {even-k sum, odd-k sum} for m0, m1
            #pragma unroll
            for (int i2 = 0; i2 < 32; ++i2) {
                ull wv0 = *reinterpret_cast<const ull*>(wp1 + 4 * i2);
                ull wv1 = *reinterpret_cast<const ull*>(wp1 + 4 * i2 + 2);
                ulonglong2 h0 = *reinterpret_cast<const ulonglong2*>(h0p + 4 * i2);
                ulonglong2 h1 = *reinterpret_cast<const ulonglong2*>(h1p + 4 * i2);
                ffma2(a0, wv0, h0.x); ffma2(a0, wv1, h0.y);
                ffma2(a1, wv0, h1.x); ffma2(a1, wv1, h1.y);
            }
            *reinterpret_cast<ulonglong2*>(sm + STG_G + (ks * 64 + jg) * 4) =
                make_ulonglong2(a0, a1);
        }
        bar_named(barid);
        if (gtid < 64) {           // reduce 4 k-chunks + horizontal + tanh
            const int j = gtid;
            ull s0 = 0, s1 = 0;
            #pragma unroll
            for (int q = 0; q < 4; ++q) {
                ulonglong2 v = *reinterpret_cast<const ulonglong2*>(
                    sm + STG_G + (q * 64 + j) * 4);
                s0 = addf2(s0, v.x);
                s1 = addf2(s1, v.y);
            }
            float b = bias_s[j], e0, o0, e1, o1;
            unpack2(e0, o0, s0);
            unpack2(e1, o1, s1);
            float p0 = tanhf(e0 + o0 + b);
            float p1 = tanhf(e1 + o1 + b);
            *reinterpret_cast<ulonglong2*>(sm + PD_G + j * 4) =
                make_ulonglong2(pack2(p0), pack2(p1));
        }
        bar_named(barid);

        // ---- GEMM2: k-pair per thread over all 64 j; scatter 16B ----
        {
            ull c0 = 0, c1 = 0;    // {k0,k1} accum for m0, m1
            const float* wp2 = sm + W_OFF + 2 * kp;
            #pragma unroll 16
            for (int j = 0; j < 64; ++j) {
                ull wv = *reinterpret_cast<const ull*>(wp2 + j * WS);
                ulonglong2 pv = *reinterpret_cast<const ulonglong2*>(sm + PD_G + j * 4);
                ffma2(c0, wv, pv.x);
                ffma2(c1, wv, pv.y);
            }
            st_dsm_v2(red_dst, c0, c1);
            __syncwarp();
            if (lane0) mbar_arrive_remote(red_arr);
        }

        // ---- owner update (gtid < 128): wait + reduce 8 srcs ----
        if (gtid < 128) {
            mbar_wait(redM, (uint32_t)(t & 1));

            int tn = (t + 1 < T_LEN) ? (t + 1) : (T_LEN - 1);
            float tI_next = g_tanhI[row_base + (size_t)tn * NH];

            const int klp = kl_u >> 1, par = kl_u & 1;
            const int ridx = klp * 4 + m_u * 2 + par;
            float s = 0.f;
            #pragma unroll
            for (int src = 0; src < 8; ++src)
                s += sm[RED_G + src * 128 + ridx];

            hz_r = hz_r + DT_C * (tI - s - g_r * hy_r - e_r * hz_r);
            hy_r = hy_r + DT_C * hz_r;
            tI = tI_next;

            out_states[(size_t)(m_base + 2 * g + m_u) * T_LEN * NH +
                       (size_t)t * NH + k_own] = hy_r;
            sm[HYST_G + m_u * 72 + kl_u] = hy_r;
        }
        bar_named(barid);

        // ---- broadcast hy slice into every rank's hyT (skip last step) ----
        if (t + 1 < T_LEN) {
            ulonglong2 hv = *reinterpret_cast<const ulonglong2*>(
                sm + HYST_G + bc_m * 72 + bc_q * 4);
            st_dsm_v2(hy_dst, hv.x, hv.y);
            __syncwarp();
            if (lane0) mbar_arrive_remote(hy_arr);
        }
    }

    if (gtid < 128 && out_hy)
        out_hy[(size_t)(m_base + 2 * g + m_u) * NH + k_own] = hy_r;

    cluster_sync_();   // no CTA exits while peers' DSMEM traffic may target it
}

// ---------------------------------------------------------------------------
extern "C" void kernel_launch(void* const* d_in, const int* in_sizes, int n_in,
                              void* d_out, int out_size) {
    const float* x    = (const float*)d_in[0];
    const float* x2h  = (const float*)d_in[1];
    const float* h2h  = (const float*)d_in[2];
    const float* bias = (const float*)d_in[3];
    const float* gam  = (const float*)d_in[4];
    const float* eps  = (const float*)d_in[5];
    float* out = (float*)d_out;

    const long long BTH = (long long)BSZ * T_LEN * NH;
    float* states = nullptr;
    float* hyout  = nullptr;
    if ((long long)out_size >= BTH) {
        states = out;
        if ((long long)out_size >= BTH + (long long)BSZ * NH) hyout = out + BTH;
    } else {
        hyout = out;
    }

    phase1_kernel<<<(BSZ * T_LEN) / 16, 256>>>(x, x2h);

    cudaFuncSetAttribute(rnn_kernel, cudaFuncAttributeMaxDynamicSharedMemorySize,
                         SMEM_BYTES);

    cudaLaunchConfig_t cfg = {};
    cfg.gridDim = dim3(128, 1, 1);
    cfg.blockDim = dim3(512, 1, 1);
    cfg.dynamicSmemBytes = SMEM_BYTES;
    cfg.stream = 0;
    cudaLaunchAttribute attrs[1];
    attrs[0].id = cudaLaunchAttributeClusterDimension;
    attrs[0].val.clusterDim.x = 8;
    attrs[0].val.clusterDim.y = 1;
    attrs[0].val.clusterDim.z = 1;
    cfg.attrs = attrs;
    cfg.numAttrs = 1;
    cudaLaunchKernelEx(&cfg, rnn_kernel, h2h, bias, gam, eps, states, hyout);
}

// round 11
// speedup vs baseline: 1.3328x; 1.3328x over previous
#include <cuda_runtime.h>
#include <cuda_bf16.h>
#include <cstdint>
#include <cmath>

#define T_LEN 1024
#define NH    512
#define NI    128
#define BSZ   64
#define DT_C  0.1f

// Hoisted input projection scratch: tanh(x @ x2h), [B, T, H] fp32 (134 MB).
__device__ float g_tanhI[(size_t)BSZ * T_LEN * NH];

typedef unsigned long long ull;

// ---------------------------------------------------------------------------
// helpers
// ---------------------------------------------------------------------------
__device__ __forceinline__ uint32_t smem_u32(const void* p) {
    uint32_t a;
    asm("{ .reg .u64 t; cvta.to.shared.u64 t, %1; cvt.u32.u64 %0, t; }" : "=r"(a) : "l"(p));
    return a;
}
__device__ __forceinline__ uint32_t mapa_sc(uint32_t addr, uint32_t rank) {
    uint32_t r;
    asm("mapa.shared::cluster.u32 %0, %1, %2;" : "=r"(r) : "r"(addr), "r"(rank));
    return r;
}
__device__ __forceinline__ void cluster_sync_() {
    asm volatile("barrier.cluster.arrive.aligned;" ::: "memory");
    asm volatile("barrier.cluster.wait.aligned;" ::: "memory");
}
__device__ __forceinline__ ull pack2(float w) {
    ull r;
    asm("mov.b64 %0, {%1, %1};" : "=l"(r) : "f"(w));
    return r;
}
__device__ __forceinline__ void ffma2(ull& d, ull a, ull b) {
    asm("fma.rn.f32x2 %0, %1, %2, %0;" : "+l"(d) : "l"(a), "l"(b));
}
__device__ __forceinline__ void mbar_init(uint32_t addr, uint32_t count) {
    asm volatile("mbarrier.init.shared.b64 [%0], %1;" :: "r"(addr), "r"(count) : "memory");
}
__device__ __forceinline__ void mbar_expect(uint32_t addr, uint32_t bytes) {
    asm volatile("mbarrier.arrive.expect_tx.shared.b64 _, [%0], %1;"
                 :: "r"(addr), "r"(bytes) : "memory");
}
__device__ __forceinline__ void mbar_wait(uint32_t mbar, uint32_t parity) {
    uint32_t done;
    asm volatile(
        "{\n\t.reg .pred p;\n\t"
        "mbarrier.try_wait.parity.acquire.cluster.shared::cta.b64 p, [%1], %2;\n\t"
        "selp.b32 %0, 1, 0, p;\n\t}"
        : "=r"(done) : "r"(mbar), "r"(parity) : "memory");
    if (!done) {
        asm volatile(
            "{\n\t.reg .pred P1;\n\t"
            "W_%=:\n\t"
            "mbarrier.try_wait.parity.acquire.cluster.shared::cta.b64 P1, [%0], %1, 0x989680;\n\t"
            "@P1 bra.uni D_%=;\n\t"
            "bra.uni W_%=;\n\t"
            "D_%=:\n\t}"
            :: "r"(mbar), "r"(parity) : "memory");
    }
}
__device__ __forceinline__ void fence_async_() {
    asm volatile("fence.proxy.async.shared::cta;" ::: "memory");
}
// CTA->cluster bulk copy with remote complete_tx
__device__ __forceinline__ void bulk_dsm(uint32_t dst_cluster, uint32_t src_cta,
                                         uint32_t bytes, uint32_t mbar_cluster) {
    asm volatile(
        "cp.async.bulk.shared::cluster.shared::cta.mbarrier::complete_tx::bytes "
        "[%0], [%1], %2, [%3];"
        :: "r"(dst_cluster), "r"(src_cta), "r"(bytes), "r"(mbar_cluster) : "memory");
}

// ---------------------------------------------------------------------------
// Phase 1: g_tanhI[bt, h] = tanh( x[bt, :] @ x2h[:, h] )
// ---------------------------------------------------------------------------
__global__ void __launch_bounds__(256) phase1_kernel(const float* __restrict__ x,
                                                     const float* __restrict__ x2h) {
    __shared__ float  x_s[16 * 132];
    __shared__ float4 w4_s[128 * 16];
    const int tid = threadIdx.x;
    const int bt0 = blockIdx.x * 16;

    for (int i = tid; i < 512; i += 256) {
        int r = i >> 5, c = i & 31;
        float4 v = *reinterpret_cast<const float4*>(x + (size_t)(bt0 + r) * NI + c * 4);
        *reinterpret_cast<float4*>(x_s + r * 132 + c * 4) = v;
    }

    const int tt = tid & 15;
    const int jc = tid >> 4;
    for (int chunk = 0; chunk < 8; ++chunk) {
        __syncthreads();
        const int jbase = chunk * 64;
        for (int i = tid; i < 2048; i += 256) {
            int k = i >> 4, jq = i & 15;
            w4_s[k * 16 + jq] =
                *reinterpret_cast<const float4*>(x2h + (size_t)k * NH + jbase + jq * 4);
        }
        __syncthreads();
        float a0 = 0.f, a1 = 0.f, a2 = 0.f, a3 = 0.f;
        #pragma unroll 8
        for (int k = 0; k < 128; ++k) {
            float  xv = x_s[tt * 132 + k];
            float4 w  = w4_s[k * 16 + jc];
            a0 = fmaf(xv, w.x, a0); a1 = fmaf(xv, w.y, a1);
            a2 = fmaf(xv, w.z, a2); a3 = fmaf(xv, w.w, a3);
        }
        float4 o = make_float4(tanhf(a0), tanhf(a1), tanhf(a2), tanhf(a3));
        *reinterpret_cast<float4*>(g_tanhI + (size_t)(bt0 + tt) * NH + jbase + jc * 4) = o;
    }
}

// ---------------------------------------------------------------------------
// Phase 2: recurrence. 16 clusters x 8 CTAs x 512 threads (R3 compute).
// Exchanges via cp.async.bulk CTA->cluster (8 x 1KB per exchange) with
// tx-mbarrier completion; NO per-thread remote stores, NO in-loop cluster.sync.
//
// SMEM float layout:
//   [0)      wT      64*513 = 32832
//   [32832)  hy4     512*4    (hy[k][m]; block src = 1KB at src*256 floats)
//   [34880)  pre     64*4
//   [35136)  stage   8*64*4
//   [37184)  red     8*64*4   ([src][kl][m]; 1KB blocks)
//   [39232)  redout  8*64*4   (local staging [tgt][kl][m])
//   [41280)  hyst    64*4     ([kl][m])
//   [41536)  bias    64
//   [41600)  mbars   red_mbar(8B) + hy_mbar(8B) = 4 floats
//   total 41604 floats = 166416 B
// ---------------------------------------------------------------------------
#define WS        513
#define W_OFF     0
#define HY_OFF    32832
#define PRE_OFF   34880
#define STG_OFF   35136
#define RED_OFF   37184
#define RDO_OFF   39232
#define HYST_OFF  41280
#define BIAS_OFF  41536
#define MBAR_OFF  41600
#define SMEM_FLOATS 41604
#define SMEM_BYTES  (SMEM_FLOATS * 4)

__global__ void __launch_bounds__(512)
rnn_kernel(const float* __restrict__ h2h, const float* __restrict__ bias,
           const float* __restrict__ gamma_v, const float* __restrict__ eps_v,
           float* __restrict__ out_states, float* __restrict__ out_hy) {
    extern __shared__ float sm[];
    float* bias_s = sm + BIAS_OFF;
    ulonglong2* stg2 = reinterpret_cast<ulonglong2*>(sm + STG_OFF);

    const int tid = threadIdx.x;
    uint32_t rank;
    asm("mov.u32 %0, %%cluster_ctarank;" : "=r"(rank));
    const int m_base = (blockIdx.x >> 3) * 4;
    const int J0 = (int)rank * 64;
    const uint32_t smb = smem_u32(sm);
    const uint32_t red_mbar = smb + MBAR_OFF * 4;
    const uint32_t hy_mbar  = smb + MBAR_OFF * 4 + 8;

    // --- init: weights, bias, zero hy4, mbars + phase-0 expects ---
    for (int idx = tid; idx < 64 * 512; idx += 512) {
        int k = idx >> 6, jl = idx & 63;
        sm[W_OFF + jl * WS + k] = h2h[(size_t)k * NH + J0 + jl];
    }
    if (tid < 64) bias_s[tid] = bias[J0 + tid];
    for (int i = tid; i < 2048; i += 512) sm[HY_OFF + i] = 0.f;
    if (tid == 0) {
        mbar_init(red_mbar, 1);
        mbar_init(hy_mbar, 1);
        mbar_expect(red_mbar, 8192);   // phase 0
        mbar_expect(hy_mbar, 8192);    // phase 0
    }

    // --- fixed thread mappings (R3) ---
    const int ks = tid >> 6;          // GEMM1 k-split 0..7 (64 k each)
    const int jg = tid & 63;          // GEMM1 local j
    const int k2 = tid;               // GEMM2 k (0..511)
    const int kl_u = tid >> 2;        // update (tid<256): [kl][m]
    const int m_u  = tid & 3;
    const int k_own = J0 + kl_u;

    // bulk-copy descriptors (threads 256..263 are the issuers; peer p = tid-256)
    uint32_t red_dst = 0, red_src = 0, red_mb = 0;
    uint32_t hy_dst = 0, hy_src = 0, hy_mb = 0;
    if (tid >= 256 && tid < 264) {
        const uint32_t p = (uint32_t)(tid - 256);
        red_dst = mapa_sc(smb + RED_OFF * 4, p) + rank * 1024;
        red_src = smb + RDO_OFF * 4 + p * 1024;
        red_mb  = mapa_sc(red_mbar, p);
        hy_dst  = mapa_sc(smb + HY_OFF * 4, p) + rank * 1024;
        hy_src  = smb + HYST_OFF * 4;
        hy_mb   = mapa_sc(hy_mbar, p);
    }

    float hy_r = 0.f, hz_r = 0.f, g_r = 0.f, e_r = 0.f, tI = 0.f;
    size_t row_base = 0;
    if (tid < 256) {
        g_r = gamma_v[k_own];
        e_r = eps_v[k_own];
        row_base = (size_t)(m_base + m_u) * T_LEN * NH + k_own;
        tI = g_tanhI[row_base];
    }

    __syncthreads();
    cluster_sync_();   // weights/zeroed-hy/mbars visible before any bulk lands

    const float* wcol1 = sm + W_OFF + jg * WS + ks * 64;
    const ulonglong2* hyk  = reinterpret_cast<const ulonglong2*>(sm + HY_OFF) + ks * 64;
    const ulonglong2* pre2 = reinterpret_cast<const ulonglong2*>(sm + PRE_OFF);

    for (int t = 0; t < T_LEN; ++t) {
        // ---- wait hy bulk delivery (phase t-1), re-arm next hy phase ----
        if (t) {
            mbar_wait(hy_mbar, (uint32_t)((t + 1) & 1));   // phase t-1 parity
            if (tid == 0 && t <= T_LEN - 2) mbar_expect(hy_mbar, 8192);
        }

        // ---- GEMM1 k-split partial: stage[ks][jg][m0..3] ----
        {
            ull a01 = 0ull, a23 = 0ull;
            #pragma unroll 16
            for (int k = 0; k < 64; ++k) {
                ull w2 = pack2(wcol1[k]);
                ulonglong2 h = hyk[k];
                ffma2(a01, w2, h.x);
                ffma2(a23, w2, h.y);
            }
            stg2[ks * 64 + jg] = make_ulonglong2(a01, a23);
        }
        __syncthreads();
        if (tid < 256) {                 // sum 8 partials + bias + tanh
            float s = bias_s[tid >> 2];
            #pragma unroll
            for (int q = 0; q < 8; ++q) s += sm[STG_OFF + q * 256 + tid];
            sm[PRE_OFF + tid] = tanhf(s);
        }
        __syncthreads();

        // ---- GEMM2 partial: 1 k/thread over my 64-j slice -> LOCAL staging ----
        {
            ull b01 = 0ull, b23 = 0ull;
            #pragma unroll 16
            for (int j = 0; j < 64; ++j) {
                ull w2 = pack2(sm[W_OFF + j * WS + k2]);
                ulonglong2 p = pre2[j];
                ffma2(b01, w2, p.x);
                ffma2(b23, w2, p.y);
            }
            *reinterpret_cast<ulonglong2*>(
                sm + RDO_OFF + ((k2 >> 6) * 256 + (k2 & 63) * 4)) =
                make_ulonglong2(b01, b23);
        }
        __syncthreads();                 // staging complete (STS drained)

        // ---- 8 x 1KB red bulk copies (issuers: tid 256..263) ----
        if (tid >= 256 && tid < 264) {
            fence_async_();
            bulk_dsm(red_dst, red_src, 1024, red_mb);
        }

        // ---- owner update: wait red tx, re-arm, reduce, integrate ----
        if (tid < 256) {
            int tn = (t + 1 < T_LEN) ? (t + 1) : (T_LEN - 1);
            float tI_next = g_tanhI[row_base + (size_t)tn * NH];   // overlap wait

            mbar_wait(red_mbar, (uint32_t)(t & 1));
            if (tid == 0 && t + 1 < T_LEN) mbar_expect(red_mbar, 8192);

            float s = 0.f;
            #pragma unroll
            for (int src = 0; src < 8; ++src) s += sm[RED_OFF + src * 256 + tid];

            hz_r = hz_r + DT_C * (tI - s - g_r * hy_r - e_r * hz_r);
            hy_r = hy_r + DT_C * hz_r;
            tI = tI_next;

            out_states[(size_t)(m_base + m_u) * T_LEN * NH + (size_t)t * NH + k_own] = hy_r;
            sm[HYST_OFF + tid] = hy_r;   // [kl][m] staging
        }
        __syncthreads();                 // hyst complete

        // ---- 8 x 1KB hy bulk copies (skip after last step) ----
        if (t + 1 < T_LEN && tid >= 256 && tid < 264) {
            fence_async_();
            bulk_dsm(hy_dst, hy_src, 1024, hy_mb);
        }
    }

    if (tid < 256 && out_hy)
        out_hy[(size_t)(m_base + m_u) * NH + k_own] = hy_r;

    cluster_sync_();   // keep smem alive until all peer traffic settles
}

// ---------------------------------------------------------------------------
extern "C" void kernel_launch(void* const* d_in, const int* in_sizes, int n_in,
                              void* d_out, int out_size) {
    const float* x    = (const float*)d_in[0];
    const float* x2h  = (const float*)d_in[1];
    const float* h2h  = (const float*)d_in[2];
    const float* bias = (const float*)d_in[3];
    const float* gam  = (const float*)d_in[4];
    const float* eps  = (const float*)d_in[5];
    float* out = (float*)d_out;

    const long long BTH = (long long)BSZ * T_LEN * NH;
    float* states = nullptr;
    float* hyout  = nullptr;
    if ((long long)out_size >= BTH) {
        states = out;
        if ((long long)out_size >= BTH + (long long)BSZ * NH) hyout = out + BTH;
    } else {
        hyout = out;
    }

    phase1_kernel<<<(BSZ * T_LEN) / 16, 256>>>(x, x2h);

    cudaFuncSetAttribute(rnn_kernel, cudaFuncAttributeMaxDynamicSharedMemorySize,
                         SMEM_BYTES);

    cudaLaunchConfig_t cfg = {};
    cfg.gridDim = dim3(128, 1, 1);
    cfg.blockDim = dim3(512, 1, 1);
    cfg.dynamicSmemBytes = SMEM_BYTES;
    cfg.stream = 0;
    cudaLaunchAttribute attrs[1];
    attrs[0].id = cudaLaunchAttributeClusterDimension;
    attrs[0].val.clusterDim.x = 8;
    attrs[0].val.clusterDim.y = 1;
    attrs[0].val.clusterDim.z = 1;
    cfg.attrs = attrs;
    cfg.numAttrs = 1;
    cudaLaunchKernelEx(&cfg, rnn_kernel, h2h, bias, gam, eps, states, hyout);
}